// round 2
// baseline (speedup 1.0000x reference)
#include <cuda_runtime.h>
#include <math.h>
#include <stdint.h>

#define BATCH 64
#define SEQ   2048
#define IN_F  256
#define HID   512

// ---------------------------------------------------------------------------
// Packed f32x2 helpers (sm_100+ PTX; FFMA2 is 2x FFMA throughput per issue)
// ---------------------------------------------------------------------------
__device__ __forceinline__ unsigned long long ffma2(unsigned long long a,
                                                    unsigned long long b,
                                                    unsigned long long c) {
    unsigned long long d;
    asm("fma.rn.f32x2 %0, %1, %2, %3;" : "=l"(d) : "l"(a), "l"(b), "l"(c));
    return d;
}
__device__ __forceinline__ unsigned long long dup2(float x) {
    unsigned long long d;
    asm("mov.b64 %0, {%1, %1};" : "=l"(d) : "f"(x));
    return d;
}
__device__ __forceinline__ float f2lo(unsigned long long v) {
    return __int_as_float((int)(unsigned int)(v & 0xffffffffULL));
}
__device__ __forceinline__ float f2hi(unsigned long long v) {
    return __int_as_float((int)(unsigned int)(v >> 32));
}

// W_hh transposed: g_Wt[k*HID + j] = W_hh[j*HID + k]  (1 MB, L2-resident)
__device__ float g_Wt[HID * HID];

// ---------------------------------------------------------------------------
// Kernel 0: transpose W_hh
// ---------------------------------------------------------------------------
__global__ void transpose_whh(const float* __restrict__ Whh) {
    int idx = blockIdx.x * blockDim.x + threadIdx.x;
    if (idx < HID * HID) {
        int j = idx >> 9;          // idx / 512
        int k = idx & (HID - 1);   // idx % 512
        g_Wt[k * HID + j] = Whh[j * HID + k];
    }
}

// ---------------------------------------------------------------------------
// Kernel 1: x_proj GEMM  out[m][n] = sum_k X[m][k]*Wih[n][k] + bih[n] + bhh[n]
// M = B*S = 131072, K = 256, N = 512.  Written in-place into d_out.
// Tile: 128(M) x 64(N) x 32(K), 256 threads, 8x4 micro-tile, f32x2 packed.
// ---------------------------------------------------------------------------
#define BM 128
#define BN 64
#define BK 32
#define ASP 130   // padded pitch for As (bank-conflict mitigation, 8B aligned)

__global__ __launch_bounds__(256) void xproj_kernel(
    const float* __restrict__ X, const float* __restrict__ Wih,
    const float* __restrict__ bih, const float* __restrict__ bhh,
    float* __restrict__ out)
{
    __shared__ float As[BK][ASP];   // As[k][m] (transposed A tile)
    __shared__ float Ws[BK][BN];    // Ws[k][n] (transposed W tile)

    const int tid = threadIdx.x;
    const int m0 = blockIdx.x * BM;
    const int n0 = blockIdx.y * BN;
    const int tx = tid & 15;        // 16 col-groups of 4
    const int ty = tid >> 4;        // 16 row-groups of 8

    unsigned long long acc[4][4];   // [m-pair][n], packed over m
#pragma unroll
    for (int r = 0; r < 4; r++)
#pragma unroll
        for (int c = 0; c < 4; c++) acc[r][c] = 0ULL;

    for (int k0 = 0; k0 < IN_F; k0 += BK) {
        // Load A tile: 128x32 floats = 1024 float4, 4 per thread
#pragma unroll
        for (int i = 0; i < 4; i++) {
            int idx = tid + i * 256;
            int m = idx >> 3;
            int k4 = idx & 7;
            float4 v = *(const float4*)(X + (size_t)(m0 + m) * IN_F + k0 + k4 * 4);
            As[k4 * 4 + 0][m] = v.x;
            As[k4 * 4 + 1][m] = v.y;
            As[k4 * 4 + 2][m] = v.z;
            As[k4 * 4 + 3][m] = v.w;
        }
        // Load W tile: 64x32 floats = 512 float4, 2 per thread
#pragma unroll
        for (int i = 0; i < 2; i++) {
            int idx = tid + i * 256;
            int n = idx >> 3;
            int k4 = idx & 7;
            float4 v = *(const float4*)(Wih + (size_t)(n0 + n) * IN_F + k0 + k4 * 4);
            Ws[k4 * 4 + 0][n] = v.x;
            Ws[k4 * 4 + 1][n] = v.y;
            Ws[k4 * 4 + 2][n] = v.z;
            Ws[k4 * 4 + 3][n] = v.w;
        }
        __syncthreads();

#pragma unroll
        for (int k = 0; k < BK; k++) {
            unsigned long long ap[4];
#pragma unroll
            for (int r = 0; r < 4; r++)
                ap[r] = *(const unsigned long long*)&As[k][ty * 8 + 2 * r];
            float4 wv = *(const float4*)&Ws[k][tx * 4];
            unsigned long long wd0 = dup2(wv.x), wd1 = dup2(wv.y);
            unsigned long long wd2 = dup2(wv.z), wd3 = dup2(wv.w);
#pragma unroll
            for (int r = 0; r < 4; r++) {
                acc[r][0] = ffma2(ap[r], wd0, acc[r][0]);
                acc[r][1] = ffma2(ap[r], wd1, acc[r][1]);
                acc[r][2] = ffma2(ap[r], wd2, acc[r][2]);
                acc[r][3] = ffma2(ap[r], wd3, acc[r][3]);
            }
        }
        __syncthreads();
    }

    float bsum[4];
#pragma unroll
    for (int c = 0; c < 4; c++) {
        int n = n0 + tx * 4 + c;
        bsum[c] = bih[n] + bhh[n];
    }
#pragma unroll
    for (int r = 0; r < 4; r++) {
        size_t mlo = (size_t)(m0 + ty * 8 + 2 * r);
        float4 lo4, hi4;
        lo4.x = f2lo(acc[r][0]) + bsum[0]; lo4.y = f2lo(acc[r][1]) + bsum[1];
        lo4.z = f2lo(acc[r][2]) + bsum[2]; lo4.w = f2lo(acc[r][3]) + bsum[3];
        hi4.x = f2hi(acc[r][0]) + bsum[0]; hi4.y = f2hi(acc[r][1]) + bsum[1];
        hi4.z = f2hi(acc[r][2]) + bsum[2]; hi4.w = f2hi(acc[r][3]) + bsum[3];
        *(float4*)(out + mlo * HID + n0 + tx * 4)       = lo4;
        *(float4*)(out + (mlo + 1) * HID + n0 + tx * 4) = hi4;
    }
}

// ---------------------------------------------------------------------------
// Kernel 2: sequential scan. One CTA handles 2 batch rows for all timesteps.
// 512 threads: tid -> (half = tid>>7 gives k-quarter, colg = tid&127 gives
// 4 output columns). h kept in smem duplicate-packed (f32x2) for FFMA2.
// xp is read from d_out and overwritten in-place with h.
// ---------------------------------------------------------------------------
__global__ __launch_bounds__(512) void scan_kernel(
    const float* __restrict__ h0, float* __restrict__ out)
{
    __shared__ unsigned long long hsd[2][HID];   // dup-packed h, 8 KB
    __shared__ float psum[4][2][HID];            // partial sums, 16 KB

    const int tid  = threadIdx.x;
    const int half = tid >> 7;          // 0..3 (k-quarter)
    const int colg = tid & 127;         // column group (4 cols)
    const int k0   = half * 128;
    const int b0   = blockIdx.x * 2;

    // init h from h0
    for (int i = tid; i < 2 * HID; i += 512) {
        int b = i >> 9;
        int j = i & (HID - 1);
        float v = h0[(size_t)(b0 + b) * HID + j];
        hsd[b][j] = dup2(v);
    }
    __syncthreads();

    const ulonglong2* __restrict__ WT = (const ulonglong2*)g_Wt;  // [512][128]

    for (int t = 0; t < SEQ; t++) {
        unsigned long long a0x = 0, a0z = 0, a1x = 0, a1z = 0;
#pragma unroll 4
        for (int k = k0; k < k0 + 128; k++) {
            ulonglong2 w = WT[k * 128 + colg];     // 4 consecutive W^T floats
            unsigned long long hd0 = hsd[0][k];    // (h0[k], h0[k])
            unsigned long long hd1 = hsd[1][k];    // (h1[k], h1[k])
            a0x = ffma2(w.x, hd0, a0x);
            a0z = ffma2(w.y, hd0, a0z);
            a1x = ffma2(w.x, hd1, a1x);
            a1z = ffma2(w.y, hd1, a1z);
        }
        {
            int c4 = colg * 4;
            float4 p0, p1;
            p0.x = f2lo(a0x); p0.y = f2hi(a0x); p0.z = f2lo(a0z); p0.w = f2hi(a0z);
            p1.x = f2lo(a1x); p1.y = f2hi(a1x); p1.z = f2lo(a1z); p1.w = f2hi(a1z);
            *(float4*)&psum[half][0][c4] = p0;
            *(float4*)&psum[half][1][c4] = p1;
        }
        __syncthreads();

        // reduce k-quarters, add xp, tanh, update h, write output in-place
        {
            float v0 = psum[0][0][tid] + psum[1][0][tid] +
                       psum[2][0][tid] + psum[3][0][tid];
            float v1 = psum[0][1][tid] + psum[1][1][tid] +
                       psum[2][1][tid] + psum[3][1][tid];
            size_t o0 = ((size_t)b0 * SEQ + t) * HID + tid;
            size_t o1 = ((size_t)(b0 + 1) * SEQ + t) * HID + tid;
            v0 = tanhf(v0 + out[o0]);
            v1 = tanhf(v1 + out[o1]);
            out[o0] = v0;
            out[o1] = v1;
            hsd[0][tid] = dup2(v0);
            hsd[1][tid] = dup2(v1);
        }
        __syncthreads();
    }
}

// ---------------------------------------------------------------------------
// Launch
// ---------------------------------------------------------------------------
extern "C" void kernel_launch(void* const* d_in, const int* in_sizes, int n_in,
                              void* d_out, int out_size) {
    const float* x_in = (const float*)d_in[0];
    const float* h0   = (const float*)d_in[1];
    const float* W_ih = (const float*)d_in[2];
    const float* W_hh = (const float*)d_in[3];
    const float* b_ih = (const float*)d_in[4];
    const float* b_hh = (const float*)d_in[5];
    float* out = (float*)d_out;

    transpose_whh<<<(HID * HID + 255) / 256, 256>>>(W_hh);

    dim3 gg((BATCH * SEQ) / BM, HID / BN);
    xproj_kernel<<<gg, 256>>>(x_in, W_ih, b_ih, b_hh, out);

    scan_kernel<<<BATCH / 2, 512>>>(h0, out);
}

// round 3
// speedup vs baseline: 1.6973x; 1.6973x over previous
#include <cuda_runtime.h>
#include <math.h>
#include <stdint.h>

typedef unsigned long long ull;

#define BATCH 64
#define SEQ   2048
#define IN_F  256
#define HID   512
#define RANKS 8     // CTAs per cluster (each owns 64 columns of W_hh)
#define BPC   4     // batch rows per cluster

// ---------------------------------------------------------------------------
// Packed f32x2 helpers
// ---------------------------------------------------------------------------
__device__ __forceinline__ ull ffma2(ull a, ull b, ull c) {
    ull d;
    asm("fma.rn.f32x2 %0, %1, %2, %3;" : "=l"(d) : "l"(a), "l"(b), "l"(c));
    return d;
}
__device__ __forceinline__ ull addx2(ull a, ull b) {
    ull d;
    asm("add.rn.f32x2 %0, %1, %2;" : "=l"(d) : "l"(a), "l"(b));
    return d;
}
__device__ __forceinline__ ull dup2(float x) {
    ull d;
    asm("mov.b64 %0, {%1, %1};" : "=l"(d) : "f"(x));
    return d;
}
__device__ __forceinline__ ull pack2(float lo, float hi) {
    ull d;
    asm("mov.b64 %0, {%1, %2};" : "=l"(d) : "f"(lo), "f"(hi));
    return d;
}
__device__ __forceinline__ float f2lo(ull v) {
    return __int_as_float((int)(unsigned int)(v & 0xffffffffULL));
}
__device__ __forceinline__ float f2hi(ull v) {
    return __int_as_float((int)(unsigned int)(v >> 32));
}

// DSMEM store: write u64 to the same smem offset in cluster CTA `rank`
__device__ __forceinline__ void st_cluster_u64(uint32_t saddr, int rank, ull v) {
    uint32_t r;
    asm volatile("mapa.shared::cluster.u32 %0, %1, %2;" : "=r"(r) : "r"(saddr), "r"(rank));
    asm volatile("st.shared::cluster.u64 [%0], %1;" :: "r"(r), "l"(v) : "memory");
}

// ---------------------------------------------------------------------------
// Kernel 1: x_proj GEMM  out[m][n] = sum_k X[m][k]*Wih[n][k] + bih[n] + bhh[n]
// M = B*S = 131072, K = 256, N = 512.  Written in-place into d_out.
// ---------------------------------------------------------------------------
#define BM 128
#define BN 64
#define BK 32
#define ASP 130

__global__ __launch_bounds__(256) void xproj_kernel(
    const float* __restrict__ X, const float* __restrict__ Wih,
    const float* __restrict__ bih, const float* __restrict__ bhh,
    float* __restrict__ out)
{
    __shared__ float As[BK][ASP];
    __shared__ float Ws[BK][BN];

    const int tid = threadIdx.x;
    const int m0 = blockIdx.x * BM;
    const int n0 = blockIdx.y * BN;
    const int tx = tid & 15;
    const int ty = tid >> 4;

    ull acc[4][4];
#pragma unroll
    for (int r = 0; r < 4; r++)
#pragma unroll
        for (int c = 0; c < 4; c++) acc[r][c] = 0ULL;

    for (int k0 = 0; k0 < IN_F; k0 += BK) {
#pragma unroll
        for (int i = 0; i < 4; i++) {
            int idx = tid + i * 256;
            int m = idx >> 3;
            int k4 = idx & 7;
            float4 v = *(const float4*)(X + (size_t)(m0 + m) * IN_F + k0 + k4 * 4);
            As[k4 * 4 + 0][m] = v.x;
            As[k4 * 4 + 1][m] = v.y;
            As[k4 * 4 + 2][m] = v.z;
            As[k4 * 4 + 3][m] = v.w;
        }
#pragma unroll
        for (int i = 0; i < 2; i++) {
            int idx = tid + i * 256;
            int n = idx >> 3;
            int k4 = idx & 7;
            float4 v = *(const float4*)(Wih + (size_t)(n0 + n) * IN_F + k0 + k4 * 4);
            Ws[k4 * 4 + 0][n] = v.x;
            Ws[k4 * 4 + 1][n] = v.y;
            Ws[k4 * 4 + 2][n] = v.z;
            Ws[k4 * 4 + 3][n] = v.w;
        }
        __syncthreads();

#pragma unroll
        for (int k = 0; k < BK; k++) {
            ull ap[4];
#pragma unroll
            for (int r = 0; r < 4; r++)
                ap[r] = *(const ull*)&As[k][ty * 8 + 2 * r];
            float4 wv = *(const float4*)&Ws[k][tx * 4];
            ull wd0 = dup2(wv.x), wd1 = dup2(wv.y);
            ull wd2 = dup2(wv.z), wd3 = dup2(wv.w);
#pragma unroll
            for (int r = 0; r < 4; r++) {
                acc[r][0] = ffma2(ap[r], wd0, acc[r][0]);
                acc[r][1] = ffma2(ap[r], wd1, acc[r][1]);
                acc[r][2] = ffma2(ap[r], wd2, acc[r][2]);
                acc[r][3] = ffma2(ap[r], wd3, acc[r][3]);
            }
        }
        __syncthreads();
    }

    float bsum[4];
#pragma unroll
    for (int c = 0; c < 4; c++) {
        int n = n0 + tx * 4 + c;
        bsum[c] = bih[n] + bhh[n];
    }
#pragma unroll
    for (int r = 0; r < 4; r++) {
        size_t mlo = (size_t)(m0 + ty * 8 + 2 * r);
        float4 lo4, hi4;
        lo4.x = f2lo(acc[r][0]) + bsum[0]; lo4.y = f2lo(acc[r][1]) + bsum[1];
        lo4.z = f2lo(acc[r][2]) + bsum[2]; lo4.w = f2lo(acc[r][3]) + bsum[3];
        hi4.x = f2hi(acc[r][0]) + bsum[0]; hi4.y = f2hi(acc[r][1]) + bsum[1];
        hi4.z = f2hi(acc[r][2]) + bsum[2]; hi4.w = f2hi(acc[r][3]) + bsum[3];
        *(float4*)(out + mlo * HID + n0 + tx * 4)       = lo4;
        *(float4*)(out + (mlo + 1) * HID + n0 + tx * 4) = hi4;
    }
}

// ---------------------------------------------------------------------------
// Kernel 2: cluster-cooperative scan.
// 16 clusters x 8 CTAs. Cluster c handles batch rows [4c, 4c+4).
// CTA rank r owns output columns [64r, 64r+64); its W slice (512 x 64 fp32 =
// 128 KB) lives entirely in registers (128 floats / thread x 256 threads).
// h (4 batch rows x 512, packed as f32x2 pairs) lives in smem, double
// buffered; the per-step h-slice exchange goes over DSMEM with ONE
// barrier.cluster per step.
//
// Thread layout: tid = c2*8 + kq.  c2 in [0,32): owns cols {2*c2, 2*c2+1}.
// kq in [0,8): k-chunk [64*kq, 64*kq+64).  8-lane shuffle allreduce over kq.
// h smem layout: slot(k) = (k&63)*8 + (k>>6)  ->  the 8 kq lanes of a warp
// read 8 consecutive ulonglong2 = one conflict-free 128B phase.
// ---------------------------------------------------------------------------
__global__ void __cluster_dims__(RANKS, 1, 1) __launch_bounds__(256, 1)
scan_kernel(const float* __restrict__ h0, const float* __restrict__ Whh,
            float* __restrict__ out)
{
    __shared__ ulonglong2 hp[2][HID];   // [buffer][slot] : ((h0,h1),(h2,h3))

    const int tid  = threadIdx.x;
    const int kq   = tid & 7;
    const int c2   = tid >> 3;            // 0..31
    const int rank = blockIdx.x & (RANKS - 1);
    const int cid  = blockIdx.x >> 3;
    const int b0   = cid * BPC;
    const int cglob = rank * 64 + c2 * 2;

    // ---- W slice into registers: rows cglob, cglob+1; k in [64*kq, 64*kq+64)
    float w0r[64], w1r[64];
    {
        const float* r0p = Whh + (size_t)cglob * HID + kq * 64;
        const float* r1p = r0p + HID;
#pragma unroll
        for (int i4 = 0; i4 < 16; i4++) {
            float4 a = *(const float4*)(r0p + i4 * 4);
            float4 b = *(const float4*)(r1p + i4 * 4);
            w0r[4 * i4 + 0] = a.x; w0r[4 * i4 + 1] = a.y;
            w0r[4 * i4 + 2] = a.z; w0r[4 * i4 + 3] = a.w;
            w1r[4 * i4 + 0] = b.x; w1r[4 * i4 + 1] = b.y;
            w1r[4 * i4 + 2] = b.z; w1r[4 * i4 + 3] = b.w;
        }
    }

    // ---- init h buffer 0 from h0 (each CTA loads the full h it needs)
    for (int k = tid; k < HID; k += 256) {
        float v0 = h0[(size_t)(b0 + 0) * HID + k];
        float v1 = h0[(size_t)(b0 + 1) * HID + k];
        float v2 = h0[(size_t)(b0 + 2) * HID + k];
        float v3 = h0[(size_t)(b0 + 3) * HID + k];
        int slot = (k & 63) * 8 + (k >> 6);
        hp[0][slot].x = pack2(v0, v1);
        hp[0][slot].y = pack2(v2, v3);
    }
    __syncthreads();

    // ---- per-thread output assignment: one (batch, col) per thread
    const int ob   = kq >> 1;                   // batch 0..3 within cluster
    const int op   = kq & 1;                    // column parity
    const int ocol = cglob + op;                // global column
    const size_t obase = ((size_t)(b0 + ob) * SEQ) * HID + ocol;

    uint32_t hpbase = (uint32_t)__cvta_generic_to_shared(&hp[0][0]);
    // DSMEM write offset (into buffer 1-p): slot = col_loc*8 + rank
    const uint32_t wroff_slot = (uint32_t)(((c2 * 2 + op) * 8 + rank) * 16 +
                                           (ob >> 1) * 8);
    const bool writer = ((ob & 1) == 0);        // lanes holding b0/b2 pack+send

    for (int t = 0; t < SEQ; t++) {
        const int p = t & 1;
        // prefetch xp for this thread's output (DRAM latency hidden by GEMM)
        float xpv = out[obase + (size_t)t * HID];

        const ulonglong2* hb = hp[p];
        ull a01_0 = 0, a23_0 = 0, a01_1 = 0, a23_1 = 0;
#pragma unroll
        for (int i = 0; i < 64; i++) {
            ulonglong2 h2 = hb[i * 8 + kq];
            ull wd0 = dup2(w0r[i]);
            ull wd1 = dup2(w1r[i]);
            a01_0 = ffma2(wd0, h2.x, a01_0);
            a23_0 = ffma2(wd0, h2.y, a23_0);
            a01_1 = ffma2(wd1, h2.x, a01_1);
            a23_1 = ffma2(wd1, h2.y, a23_1);
        }

        // allreduce partial sums across the 8 kq lanes
#pragma unroll
        for (int m = 1; m < 8; m <<= 1) {
            a01_0 = addx2(a01_0, __shfl_xor_sync(0xffffffffu, a01_0, m));
            a23_0 = addx2(a23_0, __shfl_xor_sync(0xffffffffu, a23_0, m));
            a01_1 = addx2(a01_1, __shfl_xor_sync(0xffffffffu, a01_1, m));
            a23_1 = addx2(a23_1, __shfl_xor_sync(0xffffffffu, a23_1, m));
        }

        // this thread's output value
        ull ap = op ? (ob < 2 ? a01_1 : a23_1) : (ob < 2 ? a01_0 : a23_0);
        float val = (ob & 1) ? f2hi(ap) : f2lo(ap);
        float v = tanhf(val + xpv);
        out[obase + (size_t)t * HID] = v;

        // pack (b, b+1) pair: lane kq gets v of lane kq+2 (same col, next b)
        float vn = __shfl_down_sync(0xffffffffu, v, 2);

        if (writer) {
            ull pk = pack2(v, vn);
            uint32_t off = hpbase + (uint32_t)((1 - p) * HID * 16) + wroff_slot;
#pragma unroll
            for (int r = 0; r < RANKS; r++) st_cluster_u64(off, r, pk);
        }

        // one cluster barrier per step: release our DSMEM writes,
        // acquire everyone else's
        asm volatile("barrier.cluster.arrive.aligned;" ::: "memory");
        asm volatile("barrier.cluster.wait.aligned;" ::: "memory");
    }
}

// ---------------------------------------------------------------------------
// Launch
// ---------------------------------------------------------------------------
extern "C" void kernel_launch(void* const* d_in, const int* in_sizes, int n_in,
                              void* d_out, int out_size) {
    const float* x_in = (const float*)d_in[0];
    const float* h0   = (const float*)d_in[1];
    const float* W_ih = (const float*)d_in[2];
    const float* W_hh = (const float*)d_in[3];
    const float* b_ih = (const float*)d_in[4];
    const float* b_hh = (const float*)d_in[5];
    float* out = (float*)d_out;

    dim3 gg((BATCH * SEQ) / BM, HID / BN);
    xproj_kernel<<<gg, 256>>>(x_in, W_ih, b_ih, b_hh, out);

    scan_kernel<<<(BATCH / BPC) * RANKS, 256>>>(h0, W_hh, out);
}

// round 6
// speedup vs baseline: 2.1349x; 1.2578x over previous
#include <cuda_runtime.h>
#include <math.h>
#include <stdint.h>

typedef unsigned long long ull;

#define BATCH 64
#define SEQ   2048
#define IN_F  256
#define HID   512
#define RANKS 8     // CTAs per cluster; each owns 64 columns of W_hh
#define BPC   4     // batch rows per cluster

// region: 72 entries of 16B (64 cols + 8 duplicated for rotation wrap)
#define REGION_BYTES 1152
#define BUF_BYTES    (RANKS * REGION_BYTES)   // 9216
#define EXCH_TX      (7 * REGION_BYTES)       // 8064 incoming bytes per step

// ---------------------------------------------------------------------------
// Packed f32x2 helpers
// ---------------------------------------------------------------------------
__device__ __forceinline__ ull ffma2(ull a, ull b, ull c) {
    ull d;
    asm("fma.rn.f32x2 %0, %1, %2, %3;" : "=l"(d) : "l"(a), "l"(b), "l"(c));
    return d;
}
__device__ __forceinline__ ull addx2(ull a, ull b) {
    ull d;
    asm("add.rn.f32x2 %0, %1, %2;" : "=l"(d) : "l"(a), "l"(b));
    return d;
}
__device__ __forceinline__ ull dup2(float x) {
    ull d;
    asm("mov.b64 %0, {%1, %1};" : "=l"(d) : "f"(x));
    return d;
}
__device__ __forceinline__ ull pack2(float lo, float hi) {
    ull d;
    asm("mov.b64 %0, {%1, %2};" : "=l"(d) : "f"(lo), "f"(hi));
    return d;
}
__device__ __forceinline__ float f2lo(ull v) {
    return __int_as_float((int)(unsigned int)(v & 0xffffffffULL));
}
__device__ __forceinline__ float f2hi(ull v) {
    return __int_as_float((int)(unsigned int)(v >> 32));
}

// ---------------------------------------------------------------------------
// mbarrier / cluster primitives
// ---------------------------------------------------------------------------
__device__ __forceinline__ void mbar_init(uint32_t mbar, uint32_t cnt) {
    asm volatile("mbarrier.init.shared.b64 [%0], %1;" :: "r"(mbar), "r"(cnt) : "memory");
}
__device__ __forceinline__ void mbar_expect_tx(uint32_t mbar, uint32_t bytes) {
    asm volatile("mbarrier.arrive.expect_tx.shared.b64 _, [%0], %1;"
                 :: "r"(mbar), "r"(bytes) : "memory");
}
__device__ __forceinline__ void mbar_wait(uint32_t mbar, uint32_t parity) {
    asm volatile(
        "{\n\t"
        ".reg .pred P;\n\t"
        "WL_%=:\n\t"
        "mbarrier.try_wait.parity.acquire.cta.shared::cta.b64 P, [%0], %1, 0x989680;\n\t"
        "@P bra.uni WD_%=;\n\t"
        "bra.uni WL_%=;\n\t"
        "WD_%=:\n\t"
        "}"
        :: "r"(mbar), "r"(parity) : "memory");
}
// bulk copy: our smem region -> same offset in cluster rank r, signaling r's mbar
__device__ __forceinline__ void cluster_bulk_copy(uint32_t local_addr, uint32_t bytes,
                                                  uint32_t local_mbar, int r) {
    uint32_t rdst, rmb;
    asm volatile("mapa.shared::cluster.u32 %0, %1, %2;" : "=r"(rdst) : "r"(local_addr), "r"(r));
    asm volatile("mapa.shared::cluster.u32 %0, %1, %2;" : "=r"(rmb) : "r"(local_mbar), "r"(r));
    asm volatile(
        "cp.async.bulk.shared::cluster.shared::cta.mbarrier::complete_tx::bytes "
        "[%0], [%1], %2, [%3];"
        :: "r"(rdst), "r"(local_addr), "r"(bytes), "r"(rmb) : "memory");
}

// ---------------------------------------------------------------------------
// Kernel 1: x_proj GEMM  out[m][n] = sum_k X[m][k]*Wih[n][k] + bih[n] + bhh[n]
// ---------------------------------------------------------------------------
#define BM 128
#define BN 64
#define BK 32
#define ASP 130

__global__ __launch_bounds__(256) void xproj_kernel(
    const float* __restrict__ X, const float* __restrict__ Wih,
    const float* __restrict__ bih, const float* __restrict__ bhh,
    float* __restrict__ out)
{
    __shared__ float As[BK][ASP];
    __shared__ float Ws[BK][BN];

    const int tid = threadIdx.x;
    const int m0 = blockIdx.x * BM;
    const int n0 = blockIdx.y * BN;
    const int tx = tid & 15;
    const int ty = tid >> 4;

    ull acc[4][4];
#pragma unroll
    for (int r = 0; r < 4; r++)
#pragma unroll
        for (int c = 0; c < 4; c++) acc[r][c] = 0ULL;

    for (int k0 = 0; k0 < IN_F; k0 += BK) {
#pragma unroll
        for (int i = 0; i < 4; i++) {
            int idx = tid + i * 256;
            int m = idx >> 3;
            int k4 = idx & 7;
            float4 v = *(const float4*)(X + (size_t)(m0 + m) * IN_F + k0 + k4 * 4);
            As[k4 * 4 + 0][m] = v.x;
            As[k4 * 4 + 1][m] = v.y;
            As[k4 * 4 + 2][m] = v.z;
            As[k4 * 4 + 3][m] = v.w;
        }
#pragma unroll
        for (int i = 0; i < 2; i++) {
            int idx = tid + i * 256;
            int n = idx >> 3;
            int k4 = idx & 7;
            float4 v = *(const float4*)(Wih + (size_t)(n0 + n) * IN_F + k0 + k4 * 4);
            Ws[k4 * 4 + 0][n] = v.x;
            Ws[k4 * 4 + 1][n] = v.y;
            Ws[k4 * 4 + 2][n] = v.z;
            Ws[k4 * 4 + 3][n] = v.w;
        }
        __syncthreads();

#pragma unroll
        for (int k = 0; k < BK; k++) {
            ull ap[4];
#pragma unroll
            for (int r = 0; r < 4; r++)
                ap[r] = *(const ull*)&As[k][ty * 8 + 2 * r];
            float4 wv = *(const float4*)&Ws[k][tx * 4];
            ull wd0 = dup2(wv.x), wd1 = dup2(wv.y);
            ull wd2 = dup2(wv.z), wd3 = dup2(wv.w);
#pragma unroll
            for (int r = 0; r < 4; r++) {
                acc[r][0] = ffma2(ap[r], wd0, acc[r][0]);
                acc[r][1] = ffma2(ap[r], wd1, acc[r][1]);
                acc[r][2] = ffma2(ap[r], wd2, acc[r][2]);
                acc[r][3] = ffma2(ap[r], wd3, acc[r][3]);
            }
        }
        __syncthreads();
    }

    float bsum[4];
#pragma unroll
    for (int c = 0; c < 4; c++) {
        int n = n0 + tx * 4 + c;
        bsum[c] = bih[n] + bhh[n];
    }
#pragma unroll
    for (int r = 0; r < 4; r++) {
        size_t mlo = (size_t)(m0 + ty * 8 + 2 * r);
        float4 lo4, hi4;
        lo4.x = f2lo(acc[r][0]) + bsum[0]; lo4.y = f2lo(acc[r][1]) + bsum[1];
        lo4.z = f2lo(acc[r][2]) + bsum[2]; lo4.w = f2lo(acc[r][3]) + bsum[3];
        hi4.x = f2hi(acc[r][0]) + bsum[0]; hi4.y = f2hi(acc[r][1]) + bsum[1];
        hi4.z = f2hi(acc[r][2]) + bsum[2]; hi4.w = f2hi(acc[r][3]) + bsum[3];
        *(float4*)(out + mlo * HID + n0 + tx * 4)       = lo4;
        *(float4*)(out + (mlo + 1) * HID + n0 + tx * 4) = hi4;
    }
}

// ---------------------------------------------------------------------------
// Kernel 2: cluster scan, mbarrier-synced, bulk-copy h-exchange.
//
// 16 clusters x 8 CTAs; cluster handles 4 batch rows, CTA rank owns 64 cols.
// 512 threads: col = tid>>3 (thread's output column), kq = tid&7 (k-chunk of
// 64 = source rank kq's columns). W slice in registers: 64 floats/thread,
// loaded ROTATED: w[j] = Whh[gcol][kq*64 + ((j+kq)&63)] so that the smem h
// read  (region kq, entry kq+j)  is bank-conflict-free across the 8 kq lanes.
//
// h smem: 2 buffers x 8 regions x 72 entries x 16B. Entry c of region r =
// ((h_b0,h_b1),(h_b2,h_b3)) for k = r*64+c; entries 64..71 duplicate 0..7
// (rotation wrap pad). Each step: compute -> STS own region (+dup) ->
// expect_tx -> __syncthreads -> fence.proxy.async -> 7x cp.async.bulk to
// peers (engine-side, signals peer mbar tx). Next step waits its mbar only.
// ---------------------------------------------------------------------------
__global__ void __cluster_dims__(RANKS, 1, 1) __launch_bounds__(512, 1)
scan_kernel(const float* __restrict__ h0, const float* __restrict__ Whh,
            float* __restrict__ out)
{
    __shared__ __align__(16) char hpraw[2 * BUF_BYTES];
    __shared__ __align__(8) ull mbars[2];

    const int tid  = threadIdx.x;
    const int kq   = tid & 7;
    const int col  = tid >> 3;                 // 0..63
    const int rank = blockIdx.x & (RANKS - 1);
    const int cid  = blockIdx.x >> 3;
    const int b0   = cid * BPC;
    const int gcol = rank * 64 + col;

    // ---- W slice, rotated load (one-time, uncoalesced but tiny)
    float w[64];
    {
        const float* wrow = Whh + (size_t)gcol * HID + kq * 64;
#pragma unroll
        for (int j = 0; j < 64; j++)
            w[j] = wrow[(j + kq) & 63];
    }

    if (tid == 0) {
        mbar_init((uint32_t)__cvta_generic_to_shared(&mbars[0]), 1);
        mbar_init((uint32_t)__cvta_generic_to_shared(&mbars[1]), 1);
    }

    // ---- preload h0 into buffer 0 (each CTA loads full h for its 4 rows)
    {
        const int k = tid;                     // 512 threads, one k each
        float v0 = h0[(size_t)(b0 + 0) * HID + k];
        float v1 = h0[(size_t)(b0 + 1) * HID + k];
        float v2 = h0[(size_t)(b0 + 2) * HID + k];
        float v3 = h0[(size_t)(b0 + 3) * HID + k];
        ull lo = pack2(v0, v1), hi = pack2(v2, v3);
        int r = k >> 6, c = k & 63;
        char* e = hpraw + r * REGION_BYTES + c * 16;
        *(ull*)e = lo;
        *(ull*)(e + 8) = hi;
        if (c < 8) {                            // duplication pad
            *(ull*)(e + 1024) = lo;
            *(ull*)(e + 1024 + 8) = hi;
        }
    }
    __syncthreads();
    asm volatile("barrier.cluster.arrive.aligned;" ::: "memory");
    asm volatile("barrier.cluster.wait.aligned;" ::: "memory");

    const uint32_t hpb = (uint32_t)__cvta_generic_to_shared(hpraw);
    const uint32_t mbb = (uint32_t)__cvta_generic_to_shared(&mbars[0]);

    const bool outlane = (kq < 4);
    const size_t obase = outlane ? (((size_t)(b0 + kq) * SEQ) * HID + gcol) : 0;
    float xpv = outlane ? out[obase] : 0.0f;

    const bool writer = (kq == 0) || (kq == 2);

    for (int t = 0; t < SEQ; t++) {
        const int p = t & 1;
        if (t) mbar_wait(mbb + p * 8, ((t - 1) >> 1) & 1);

        // region of source rank kq, rotated start
        const ulonglong2* hreg =
            (const ulonglong2*)(hpraw + p * BUF_BYTES + kq * REGION_BYTES) + kq;
        ull a01 = 0, a23 = 0;
#pragma unroll
        for (int j = 0; j < 64; j++) {
            ulonglong2 h2 = hreg[j];
            ull wd = dup2(w[j]);
            a01 = ffma2(wd, h2.x, a01);
            a23 = ffma2(wd, h2.y, a23);
        }

        // prefetch next step's xp while reduction/exchange runs
        float xpn = 0.0f;
        if (outlane && t + 1 < SEQ) xpn = out[obase + (size_t)(t + 1) * HID];

        // allreduce over the 8 kq lanes
#pragma unroll
        for (int m = 1; m < 8; m <<= 1) {
            a01 = addx2(a01, __shfl_xor_sync(0xffffffffu, a01, m));
            a23 = addx2(a23, __shfl_xor_sync(0xffffffffu, a23, m));
        }

        float v = 0.0f;
        if (outlane) {
            ull ap = (kq < 2) ? a01 : a23;
            float s = (kq & 1) ? f2hi(ap) : f2lo(ap);
            v = tanhf(s + xpv);
            out[obase + (size_t)t * HID] = v;
        }
        xpv = xpn;

        float vn = __shfl_down_sync(0xffffffffu, v, 1);   // pair partner

        if (t < SEQ - 1) {
            // assemble own region of next buffer
            if (writer) {
                ull pk = pack2(v, vn);
                char* wb = hpraw + (1 - p) * BUF_BYTES + rank * REGION_BYTES +
                           col * 16 + ((kq & 2) << 2);
                *(ull*)wb = pk;
                if (col < 8) *(ull*)(wb + 1024) = pk;     // dup pad
            }
            if (tid == 0) mbar_expect_tx(mbb + (1 - p) * 8, EXCH_TX);
            __syncthreads();
            if (tid == 0) {
                asm volatile("fence.proxy.async.shared::cta;" ::: "memory");
                uint32_t src = hpb + (1 - p) * BUF_BYTES + rank * REGION_BYTES;
                uint32_t lmb = mbb + (1 - p) * 8;
#pragma unroll
                for (int d = 1; d < RANKS; d++)
                    cluster_bulk_copy(src, REGION_BYTES, lmb, (rank + d) & (RANKS - 1));
            }
        }
    }

    asm volatile("barrier.cluster.arrive.aligned;" ::: "memory");
    asm volatile("barrier.cluster.wait.aligned;" ::: "memory");
}

// ---------------------------------------------------------------------------
// Launch
// ---------------------------------------------------------------------------
extern "C" void kernel_launch(void* const* d_in, const int* in_sizes, int n_in,
                              void* d_out, int out_size) {
    const float* x_in = (const float*)d_in[0];
    const float* h0   = (const float*)d_in[1];
    const float* W_ih = (const float*)d_in[2];
    const float* W_hh = (const float*)d_in[3];
    const float* b_ih = (const float*)d_in[4];
    const float* b_hh = (const float*)d_in[5];
    float* out = (float*)d_out;

    dim3 gg((BATCH * SEQ) / BM, HID / BN);
    xproj_kernel<<<gg, 256>>>(x_in, W_ih, b_ih, b_hh, out);

    scan_kernel<<<(BATCH / BPC) * RANKS, 512>>>(h0, W_hh, out);
}